// round 1
// baseline (speedup 1.0000x reference)
#include <cuda_runtime.h>
#include <math.h>

#define BB 8
#define TT 2048
#define EE 1024
#define HH 128
#define MM (BB*TT)

// Scratch for projected Q/K/V (allocation-free: __device__ globals)
__device__ float g_Q[MM*HH];
__device__ float g_K[MM*HH];
__device__ float g_V[MM*HH];

// ---------------------------------------------------------------------------
// Kernel 1: QKV projection.  C[M,128] = x[M,1024] @ W[1024,128]
// BM=128, BN=128 (= full H), BK=8; 256 threads; 8x8 register tile per thread.
// grid = (M/128, 3)  -> blockIdx.y selects Wq/Wk/Wv and target buffer.
// ---------------------------------------------------------------------------
__global__ __launch_bounds__(256) void qkv_kernel(
    const float* __restrict__ x,
    const float* __restrict__ Wq,
    const float* __restrict__ Wk,
    const float* __restrict__ Wv)
{
    __shared__ float As[8][132];   // x tile, transposed: As[k][m], padded
    __shared__ float Bs[8][128];   // W tile: Bs[k][h]

    const int mb = blockIdx.x;
    const int w  = blockIdx.y;
    const float* Wp   = (w == 0) ? Wq : ((w == 1) ? Wk : Wv);
    float*       outp = (w == 0) ? g_Q : ((w == 1) ? g_K : g_V);

    const int tid = threadIdx.x;
    const int tx  = tid & 15;
    const int ty  = tid >> 4;
    const int m0  = mb * 128;

    // global-load indices
    const int arow = tid >> 1;          // 0..127
    const int acol = (tid & 1) * 4;     // 0 or 4
    const int brow = tid >> 5;          // 0..7
    const int bcol = (tid & 31) * 4;    // 0..124

    float acc[8][8];
#pragma unroll
    for (int i = 0; i < 8; i++)
#pragma unroll
        for (int j = 0; j < 8; j++) acc[i][j] = 0.f;

    for (int k0 = 0; k0 < EE; k0 += 8) {
        float4 av = *(const float4*)&x[(m0 + arow) * EE + k0 + acol];
        float4 bv = *(const float4*)&Wp[(k0 + brow) * HH + bcol];
        As[acol + 0][arow] = av.x;
        As[acol + 1][arow] = av.y;
        As[acol + 2][arow] = av.z;
        As[acol + 3][arow] = av.w;
        *(float4*)&Bs[brow][bcol] = bv;
        __syncthreads();

#pragma unroll
        for (int kk = 0; kk < 8; kk++) {
            float4 a0 = *(float4*)&As[kk][ty * 8];
            float4 a1 = *(float4*)&As[kk][ty * 8 + 4];
            float4 b0 = *(float4*)&Bs[kk][tx * 8];
            float4 b1 = *(float4*)&Bs[kk][tx * 8 + 4];
            float a[8] = {a0.x, a0.y, a0.z, a0.w, a1.x, a1.y, a1.z, a1.w};
            float b[8] = {b0.x, b0.y, b0.z, b0.w, b1.x, b1.y, b1.z, b1.w};
#pragma unroll
            for (int i = 0; i < 8; i++)
#pragma unroll
                for (int j = 0; j < 8; j++)
                    acc[i][j] = fmaf(a[i], b[j], acc[i][j]);
        }
        __syncthreads();
    }

#pragma unroll
    for (int i = 0; i < 8; i++) {
        float* orow = &outp[(m0 + ty * 8 + i) * HH + tx * 8];
        *(float4*)orow       = make_float4(acc[i][0], acc[i][1], acc[i][2], acc[i][3]);
        *(float4*)(orow + 4) = make_float4(acc[i][4], acc[i][5], acc[i][6], acc[i][7]);
    }
}

// ---------------------------------------------------------------------------
// Kernel 2: causal flash attention.
// One block = one (batch b, q-tile of 64 rows). 256 threads = 16x16.
// Each thread: 4 q-rows (r = 4*ty+i), score cols c = tx+16*j (j<4),
// output cols h = tx+16*j (j<8).  Online softmax.
// Shared: Qs[64][132] + Ks[64][132] + Vs[64][128] + Ps[64][68] = 117,760 B
// ---------------------------------------------------------------------------
#define QS_STRIDE 132
#define PS_STRIDE 68
#define ATTN_SMEM ((64*132 + 64*132 + 64*128 + 64*68) * 4)
#define SCALE 0.08838834764831845f   // 1/sqrt(128)

__global__ __launch_bounds__(256) void attn_kernel(float* __restrict__ out)
{
    extern __shared__ float sh[];
    float* Qs = sh;                    // [64][132]
    float* Ks = Qs + 64 * 132;         // [64][132]
    float* Vs = Ks + 64 * 132;         // [64][128]
    float* Ps = Vs + 64 * 128;         // [64][68]

    const int b  = blockIdx.y;
    const int qt = (int)gridDim.x - 1 - (int)blockIdx.x;  // heavy tiles first
    const int q0 = qt * 64;

    const int tid = threadIdx.x;
    const int tx  = tid & 15;
    const int ty  = tid >> 4;

    // ---- load Q tile (scaled) ----
    const float* Qg = g_Q + ((size_t)b * TT + q0) * HH;
    for (int t = tid; t < 64 * 32; t += 256) {
        int r  = t >> 5;
        int c4 = (t & 31) << 2;
        float4 v = *(const float4*)&Qg[r * HH + c4];
        Qs[r * QS_STRIDE + c4 + 0] = v.x * SCALE;
        Qs[r * QS_STRIDE + c4 + 1] = v.y * SCALE;
        Qs[r * QS_STRIDE + c4 + 2] = v.z * SCALE;
        Qs[r * QS_STRIDE + c4 + 3] = v.w * SCALE;
    }

    float m_i[4], l_i[4];
    float O[4][8];
#pragma unroll
    for (int i = 0; i < 4; i++) {
        m_i[i] = -1e30f;
        l_i[i] = 0.f;
#pragma unroll
        for (int j = 0; j < 8; j++) O[i][j] = 0.f;
    }

    for (int kt = 0; kt <= qt; kt++) {
        const int k0 = kt * 64;
        const float* Kg = g_K + ((size_t)b * TT + k0) * HH;
        const float* Vg = g_V + ((size_t)b * TT + k0) * HH;

        for (int t = tid; t < 64 * 32; t += 256) {
            int r  = t >> 5;
            int c4 = (t & 31) << 2;
            float4 kv = *(const float4*)&Kg[r * HH + c4];
            Ks[r * QS_STRIDE + c4 + 0] = kv.x;
            Ks[r * QS_STRIDE + c4 + 1] = kv.y;
            Ks[r * QS_STRIDE + c4 + 2] = kv.z;
            Ks[r * QS_STRIDE + c4 + 3] = kv.w;
            *(float4*)&Vs[r * 128 + c4] = *(const float4*)&Vg[r * HH + c4];
        }
        __syncthreads();

        // ---- S = Q K^T  (64x64 tile), thread owns 4x4 ----
        float s[4][4];
#pragma unroll
        for (int i = 0; i < 4; i++)
#pragma unroll
            for (int j = 0; j < 4; j++) s[i][j] = 0.f;

        for (int kk = 0; kk < HH; kk += 4) {
            float4 a[4], bk[4];
#pragma unroll
            for (int i = 0; i < 4; i++)
                a[i] = *(float4*)&Qs[(ty * 4 + i) * QS_STRIDE + kk];
#pragma unroll
            for (int j = 0; j < 4; j++)
                bk[j] = *(float4*)&Ks[(tx + 16 * j) * QS_STRIDE + kk];
#pragma unroll
            for (int i = 0; i < 4; i++)
#pragma unroll
                for (int j = 0; j < 4; j++) {
                    s[i][j] = fmaf(a[i].x, bk[j].x, s[i][j]);
                    s[i][j] = fmaf(a[i].y, bk[j].y, s[i][j]);
                    s[i][j] = fmaf(a[i].z, bk[j].z, s[i][j]);
                    s[i][j] = fmaf(a[i].w, bk[j].w, s[i][j]);
                }
        }

        // ---- causal mask on diagonal tile ----
        if (kt == qt) {
#pragma unroll
            for (int i = 0; i < 4; i++)
#pragma unroll
                for (int j = 0; j < 4; j++)
                    if (tx + 16 * j > ty * 4 + i) s[i][j] = -1e30f;
        }

        // ---- online softmax ----
#pragma unroll
        for (int i = 0; i < 4; i++) {
            float mnew = fmaxf(fmaxf(s[i][0], s[i][1]), fmaxf(s[i][2], s[i][3]));
#pragma unroll
            for (int o = 1; o < 16; o <<= 1)
                mnew = fmaxf(mnew, __shfl_xor_sync(0xffffffffu, mnew, o));
            float mtot  = fmaxf(m_i[i], mnew);
            float alpha = __expf(m_i[i] - mtot);
            m_i[i] = mtot;

            float p0 = __expf(s[i][0] - mtot);
            float p1 = __expf(s[i][1] - mtot);
            float p2 = __expf(s[i][2] - mtot);
            float p3 = __expf(s[i][3] - mtot);
            float rs = p0 + p1 + p2 + p3;
#pragma unroll
            for (int o = 1; o < 16; o <<= 1)
                rs += __shfl_xor_sync(0xffffffffu, rs, o);
            l_i[i] = l_i[i] * alpha + rs;

#pragma unroll
            for (int j = 0; j < 8; j++) O[i][j] *= alpha;

            float* prow = &Ps[(ty * 4 + i) * PS_STRIDE];
            prow[tx +  0] = p0;
            prow[tx + 16] = p1;
            prow[tx + 32] = p2;
            prow[tx + 48] = p3;
        }
        __syncthreads();

        // ---- O += P V ----
        for (int kk = 0; kk < 64; kk += 4) {
            float4 pp[4];
#pragma unroll
            for (int i = 0; i < 4; i++)
                pp[i] = *(float4*)&Ps[(ty * 4 + i) * PS_STRIDE + kk];
#pragma unroll
            for (int u = 0; u < 4; u++) {
                float vv[8];
#pragma unroll
                for (int j = 0; j < 8; j++)
                    vv[j] = Vs[(kk + u) * 128 + tx + 16 * j];
                float pu[4] = { (&pp[0].x)[u], (&pp[1].x)[u], (&pp[2].x)[u], (&pp[3].x)[u] };
#pragma unroll
                for (int i = 0; i < 4; i++)
#pragma unroll
                    for (int j = 0; j < 8; j++)
                        O[i][j] = fmaf(pu[i], vv[j], O[i][j]);
            }
        }
        __syncthreads();
    }

    // ---- epilogue ----
#pragma unroll
    for (int i = 0; i < 4; i++) {
        float inv = 1.f / l_i[i];
        float* orow = &out[((size_t)b * TT + q0 + ty * 4 + i) * HH];
#pragma unroll
        for (int j = 0; j < 8; j++)
            orow[tx + 16 * j] = O[i][j] * inv;
    }
}

// ---------------------------------------------------------------------------
extern "C" void kernel_launch(void* const* d_in, const int* in_sizes, int n_in,
                              void* d_out, int out_size)
{
    const float* x  = (const float*)d_in[0];
    const float* Wq = (const float*)d_in[1];
    const float* Wk = (const float*)d_in[2];
    const float* Wv = (const float*)d_in[3];
    float* out = (float*)d_out;

    qkv_kernel<<<dim3(MM / 128, 3), 256>>>(x, Wq, Wk, Wv);

    cudaFuncSetAttribute(attn_kernel,
                         cudaFuncAttributeMaxDynamicSharedMemorySize, ATTN_SMEM);
    attn_kernel<<<dim3(TT / 64, BB), 256, ATTN_SMEM>>>(out);
}

// round 3
// speedup vs baseline: 2.8960x; 2.8960x over previous
#include <cuda_runtime.h>

#define BB 8
#define TT 2048
#define EE 1024
#define HH 128
#define MM (BB*TT)
#define SCALE 0.08838834764831845f   // 1/sqrt(128)

// Scratch for projected Q/K/V (allocation-free: __device__ globals)
__device__ float g_Q[MM*HH];
__device__ float g_K[MM*HH];
__device__ float g_V[MM*HH];

// fp32 -> tf32 (round to nearest, ties away), kept in float storage
__device__ __forceinline__ float f2tf(float f) {
    unsigned r;
    asm("cvt.rna.tf32.f32 %0, %1;" : "=r"(r) : "f"(f));
    return __uint_as_float(r);
}

// D = A(16x8,row) * B(8x8,col) + D, tf32 inputs, fp32 accum
__device__ __forceinline__ void mma_tf32(float* c,
    unsigned a0, unsigned a1, unsigned a2, unsigned a3,
    unsigned b0, unsigned b1)
{
    asm volatile(
        "mma.sync.aligned.m16n8k8.row.col.f32.tf32.tf32.f32 "
        "{%0,%1,%2,%3},{%4,%5,%6,%7},{%8,%9},{%0,%1,%2,%3};"
        : "+f"(c[0]), "+f"(c[1]), "+f"(c[2]), "+f"(c[3])
        : "r"(a0), "r"(a1), "r"(a2), "r"(a3), "r"(b0), "r"(b1));
}

// ---------------------------------------------------------------------------
// Kernel 1: QKV projection via tf32 mma.  C[M,128] = x[M,1024] @ W[1024,128]
// BM=128, BN=128, BK=32. 256 threads = 8 warps (4x2): warp tile 32x64.
// grid = (M/128, 3)
// ---------------------------------------------------------------------------
__global__ __launch_bounds__(256) void qkv_kernel(
    const float* __restrict__ x,
    const float* __restrict__ Wq,
    const float* __restrict__ Wk,
    const float* __restrict__ Wv)
{
    __shared__ float As[128][36];   // A tile [m][k], stride 36 -> conflict-free frags
    __shared__ float Bs[32][136];   // B tile [k][n], stride 136 -> conflict-free frags

    const int mb = blockIdx.x;
    const int w3 = blockIdx.y;
    const float* Wp   = (w3 == 0) ? Wq : ((w3 == 1) ? Wk : Wv);
    float*       outp = (w3 == 0) ? g_Q : ((w3 == 1) ? g_K : g_V);

    const int tid  = threadIdx.x;
    const int lane = tid & 31;
    const int w    = tid >> 5;
    const int g    = lane >> 2;
    const int t4   = lane & 3;
    const int wm   = (w >> 1) * 32;
    const int wn   = (w & 1) * 64;
    const int m0   = mb * 128;

    float acc[2][8][4];
#pragma unroll
    for (int mt = 0; mt < 2; mt++)
#pragma unroll
        for (int nt = 0; nt < 8; nt++)
#pragma unroll
            for (int i = 0; i < 4; i++) acc[mt][nt][i] = 0.f;

    // prefetch registers
    float4 xa[4], wa[4];

    // prefetch tile k0 = 0
#pragma unroll
    for (int i = 0; i < 4; i++) {
        int lin = tid + i * 256;                 // 1024 float4 for x tile
        int r = lin >> 3, c = (lin & 7) * 4;
        xa[i] = *(const float4*)&x[(size_t)(m0 + r) * EE + c];
    }
#pragma unroll
    for (int i = 0; i < 4; i++) {
        int lin = tid + i * 256;                 // 1024 float4 for W tile
        int r = lin >> 5, c = (lin & 31) * 4;
        wa[i] = *(const float4*)&Wp[(size_t)r * HH + c];
    }

    for (int k0 = 0; k0 < EE; k0 += 32) {
        // commit prefetched tile to smem (as tf32)
#pragma unroll
        for (int i = 0; i < 4; i++) {
            int lin = tid + i * 256;
            int r = lin >> 3, c = (lin & 7) * 4;
            As[r][c + 0] = f2tf(xa[i].x);
            As[r][c + 1] = f2tf(xa[i].y);
            As[r][c + 2] = f2tf(xa[i].z);
            As[r][c + 3] = f2tf(xa[i].w);
        }
#pragma unroll
        for (int i = 0; i < 4; i++) {
            int lin = tid + i * 256;
            int r = lin >> 5, c = (lin & 31) * 4;
            Bs[r][c + 0] = f2tf(wa[i].x);
            Bs[r][c + 1] = f2tf(wa[i].y);
            Bs[r][c + 2] = f2tf(wa[i].z);
            Bs[r][c + 3] = f2tf(wa[i].w);
        }
        __syncthreads();

        // prefetch next tile
        if (k0 + 32 < EE) {
            int kn = k0 + 32;
#pragma unroll
            for (int i = 0; i < 4; i++) {
                int lin = tid + i * 256;
                int r = lin >> 3, c = (lin & 7) * 4;
                xa[i] = *(const float4*)&x[(size_t)(m0 + r) * EE + kn + c];
            }
#pragma unroll
            for (int i = 0; i < 4; i++) {
                int lin = tid + i * 256;
                int r = lin >> 5, c = (lin & 31) * 4;
                wa[i] = *(const float4*)&Wp[(size_t)(kn + r) * HH + c];
            }
        }

        // compute: 4 k-steps of 8
#pragma unroll
        for (int ks = 0; ks < 4; ks++) {
            unsigned a[2][4];
#pragma unroll
            for (int mt = 0; mt < 2; mt++) {
                a[mt][0] = __float_as_uint(As[wm + mt * 16 + g    ][ks * 8 + t4    ]);
                a[mt][1] = __float_as_uint(As[wm + mt * 16 + g + 8][ks * 8 + t4    ]);
                a[mt][2] = __float_as_uint(As[wm + mt * 16 + g    ][ks * 8 + t4 + 4]);
                a[mt][3] = __float_as_uint(As[wm + mt * 16 + g + 8][ks * 8 + t4 + 4]);
            }
#pragma unroll
            for (int nt = 0; nt < 8; nt++) {
                unsigned b0 = __float_as_uint(Bs[ks * 8 + t4    ][wn + nt * 8 + g]);
                unsigned b1 = __float_as_uint(Bs[ks * 8 + t4 + 4][wn + nt * 8 + g]);
                mma_tf32(acc[0][nt], a[0][0], a[0][1], a[0][2], a[0][3], b0, b1);
                mma_tf32(acc[1][nt], a[1][0], a[1][1], a[1][2], a[1][3], b0, b1);
            }
        }
        __syncthreads();
    }

    // epilogue
#pragma unroll
    for (int mt = 0; mt < 2; mt++) {
#pragma unroll
        for (int nt = 0; nt < 8; nt++) {
            int row = m0 + wm + mt * 16 + g;
            int col = wn + nt * 8 + 2 * t4;
            float2 v0 = make_float2(acc[mt][nt][0], acc[mt][nt][1]);
            float2 v1 = make_float2(acc[mt][nt][2], acc[mt][nt][3]);
            *(float2*)&outp[(size_t)row * HH + col]       = v0;
            *(float2*)&outp[(size_t)(row + 8) * HH + col] = v1;
        }
    }
}

// ---------------------------------------------------------------------------
// Kernel 2: causal flash attention with tf32 mma.
// Block = (batch b, 64-row q-tile), 256 threads = 8 warps.
// Warp w: row-group rg=w>>1 (16 q rows), col-half ch=w&1.
//   S tile 64x64: warp computes 16x32 (4 n-tiles), round-trip through smem Ps.
//   O tile 64x128: warp accumulates 16x64 (8 n-tiles) in registers.
// ---------------------------------------------------------------------------
#define QSS 132
#define VSS 136
#define ATTN_SMEM ((64*QSS + 64*QSS + 64*VSS + 64*QSS + 192) * 4)

__global__ __launch_bounds__(256) void attn_kernel(float* __restrict__ out)
{
    extern __shared__ float sh[];
    float* Qs  = sh;                // [64][132] tf32, pre-scaled
    float* Ks  = Qs + 64 * QSS;     // [64][132] tf32
    float* Vs  = Ks + 64 * QSS;     // [64][136] tf32
    float* Ps  = Vs + 64 * VSS;     // [64][132] scores then probs(tf32)
    float* m_s = Ps + 64 * QSS;     // [64]
    float* l_s = m_s + 64;          // [64]
    float* a_s = l_s + 64;          // [64] alpha

    const int b  = blockIdx.y;
    const int qt = (int)gridDim.x - 1 - (int)blockIdx.x;  // heavy tiles first
    const int q0 = qt * 64;

    const int tid  = threadIdx.x;
    const int lane = tid & 31;
    const int w    = tid >> 5;
    const int g    = lane >> 2;
    const int t4   = lane & 3;
    const int rg   = w >> 1;
    const int ch   = w & 1;
    const int r1   = rg * 16 + g;
    const int r2   = r1 + 8;

    // load Q tile (scaled, tf32)
    const float* Qg = g_Q + ((size_t)b * TT + q0) * HH;
#pragma unroll
    for (int i = 0; i < 8; i++) {
        int lin = tid + i * 256;               // 2048 float4
        int r = lin >> 5, c = (lin & 31) * 4;
        float4 v = *(const float4*)&Qg[(size_t)r * HH + c];
        Qs[r * QSS + c + 0] = f2tf(v.x * SCALE);
        Qs[r * QSS + c + 1] = f2tf(v.y * SCALE);
        Qs[r * QSS + c + 2] = f2tf(v.z * SCALE);
        Qs[r * QSS + c + 3] = f2tf(v.w * SCALE);
    }
    if (tid < 64) { m_s[tid] = -1e30f; l_s[tid] = 0.f; }

    float o[8][4];
#pragma unroll
    for (int nt = 0; nt < 8; nt++)
#pragma unroll
        for (int i = 0; i < 4; i++) o[nt][i] = 0.f;

    for (int kt = 0; kt <= qt; kt++) {
        const int k0 = kt * 64;
        const float* Kg = g_K + ((size_t)b * TT + k0) * HH;
        const float* Vg = g_V + ((size_t)b * TT + k0) * HH;

        __syncthreads();   // prev iter's PV reads of Ps/Vs done

        // load K,V tiles (tf32)
#pragma unroll
        for (int i = 0; i < 8; i++) {
            int lin = tid + i * 256;
            int r = lin >> 5, c = (lin & 31) * 4;
            float4 kv = *(const float4*)&Kg[(size_t)r * HH + c];
            float4 vv = *(const float4*)&Vg[(size_t)r * HH + c];
            Ks[r * QSS + c + 0] = f2tf(kv.x);
            Ks[r * QSS + c + 1] = f2tf(kv.y);
            Ks[r * QSS + c + 2] = f2tf(kv.z);
            Ks[r * QSS + c + 3] = f2tf(kv.w);
            Vs[r * VSS + c + 0] = f2tf(vv.x);
            Vs[r * VSS + c + 1] = f2tf(vv.y);
            Vs[r * VSS + c + 2] = f2tf(vv.z);
            Vs[r * VSS + c + 3] = f2tf(vv.w);
        }
        __syncthreads();

        // ---- S = Q K^T : warp computes 16x32 (4 n-tiles), K-dim 128 = 16 steps
        float s[4][4];
#pragma unroll
        for (int nt = 0; nt < 4; nt++)
#pragma unroll
            for (int i = 0; i < 4; i++) s[nt][i] = 0.f;

#pragma unroll
        for (int ks = 0; ks < 16; ks++) {
            unsigned a0 = __float_as_uint(Qs[r1 * QSS + ks * 8 + t4    ]);
            unsigned a1 = __float_as_uint(Qs[r2 * QSS + ks * 8 + t4    ]);
            unsigned a2 = __float_as_uint(Qs[r1 * QSS + ks * 8 + t4 + 4]);
            unsigned a3 = __float_as_uint(Qs[r2 * QSS + ks * 8 + t4 + 4]);
#pragma unroll
            for (int nt = 0; nt < 4; nt++) {
                int kr = ch * 32 + nt * 8 + g;   // key token index in tile
                unsigned b0 = __float_as_uint(Ks[kr * QSS + ks * 8 + t4    ]);
                unsigned b1 = __float_as_uint(Ks[kr * QSS + ks * 8 + t4 + 4]);
                mma_tf32(s[nt], a0, a1, a2, a3, b0, b1);
            }
        }

        // write S to Ps
#pragma unroll
        for (int nt = 0; nt < 4; nt++) {
            int col = ch * 32 + nt * 8 + 2 * t4;
            *(float2*)&Ps[r1 * QSS + col] = make_float2(s[nt][0], s[nt][1]);
            *(float2*)&Ps[r2 * QSS + col] = make_float2(s[nt][2], s[nt][3]);
        }
        __syncthreads();

        // ---- online softmax: thread -> row r, 16-col segment
        {
            int r   = tid >> 2;
            int seg = tid & 3;
            float* prow = &Ps[r * QSS + seg * 16];
            int rowg = q0 + r;
            int colb = k0 + seg * 16;

            float vals[16];
            float mloc = -1e30f;
#pragma unroll
            for (int c = 0; c < 16; c++) {
                float v = prow[c];
                if (kt == qt && (colb + c) > rowg) v = -1e30f;
                vals[c] = v;
                mloc = fmaxf(mloc, v);
            }
            mloc = fmaxf(mloc, __shfl_xor_sync(0xffffffffu, mloc, 1));
            mloc = fmaxf(mloc, __shfl_xor_sync(0xffffffffu, mloc, 2));

            float mold = m_s[r];
            float mtot = fmaxf(mold, mloc);
            float rs = 0.f;
#pragma unroll
            for (int c = 0; c < 16; c++) {
                float p = __expf(vals[c] - mtot);
                rs += p;
                prow[c] = f2tf(p);
            }
            rs += __shfl_xor_sync(0xffffffffu, rs, 1);
            rs += __shfl_xor_sync(0xffffffffu, rs, 2);
            if (seg == 0) {
                float alpha = __expf(mold - mtot);
                m_s[r] = mtot;
                l_s[r] = l_s[r] * alpha + rs;
                a_s[r] = alpha;
            }
        }
        __syncthreads();

        // ---- rescale O, then O += P V
        {
            float al1 = a_s[r1];
            float al2 = a_s[r2];
#pragma unroll
            for (int nt = 0; nt < 8; nt++) {
                o[nt][0] *= al1; o[nt][1] *= al1;
                o[nt][2] *= al2; o[nt][3] *= al2;
            }
        }
#pragma unroll
        for (int ks = 0; ks < 8; ks++) {
            unsigned a0 = __float_as_uint(Ps[r1 * QSS + ks * 8 + t4    ]);
            unsigned a1 = __float_as_uint(Ps[r2 * QSS + ks * 8 + t4    ]);
            unsigned a2 = __float_as_uint(Ps[r1 * QSS + ks * 8 + t4 + 4]);
            unsigned a3 = __float_as_uint(Ps[r2 * QSS + ks * 8 + t4 + 4]);
#pragma unroll
            for (int nt = 0; nt < 8; nt++) {
                int col = ch * 64 + nt * 8 + g;
                unsigned b0 = __float_as_uint(Vs[(ks * 8 + t4    ) * VSS + col]);
                unsigned b1 = __float_as_uint(Vs[(ks * 8 + t4 + 4) * VSS + col]);
                mma_tf32(o[nt], a0, a1, a2, a3, b0, b1);
            }
        }
    }

    // ---- epilogue
    {
        float inv1 = 1.f / l_s[r1];
        float inv2 = 1.f / l_s[r2];
        size_t base1 = ((size_t)b * TT + q0 + r1) * HH;
        size_t base2 = ((size_t)b * TT + q0 + r2) * HH;
#pragma unroll
        for (int nt = 0; nt < 8; nt++) {
            int col = ch * 64 + nt * 8 + 2 * t4;
            *(float2*)&out[base1 + col] = make_float2(o[nt][0] * inv1, o[nt][1] * inv1);
            *(float2*)&out[base2 + col] = make_float2(o[nt][2] * inv2, o[nt][3] * inv2);
        }
    }
}

// ---------------------------------------------------------------------------
extern "C" void kernel_launch(void* const* d_in, const int* in_sizes, int n_in,
                              void* d_out, int out_size)
{
    const float* x  = (const float*)d_in[0];
    const float* Wq = (const float*)d_in[1];
    const float* Wk = (const float*)d_in[2];
    const float* Wv = (const float*)d_in[3];
    float* out = (float*)d_out;

    qkv_kernel<<<dim3(MM / 128, 3), 256>>>(x, Wq, Wk, Wv);

    cudaFuncSetAttribute(attn_kernel,
                         cudaFuncAttributeMaxDynamicSharedMemorySize, ATTN_SMEM);
    attn_kernel<<<dim3(TT / 64, BB), 256, ATTN_SMEM>>>(out);
}